// round 1
// baseline (speedup 1.0000x reference)
#include <cuda_runtime.h>
#include <cstdint>

#define NB 8
#define NT 4096
#define NC 1024      // C_in == C_out
#define NK 3
#define NWELEM (NK*NC*NC)   // 3145728

// ---------------- device scratch (static; no allocations) ----------------
__device__ __align__(16) signed char g_wq[NK*NC*NC];   // [k][o][i], i packed 4/int
__device__ __align__(16) signed char g_xq[NB*NC*NT];   // ints: [(b*256+ig)][t], 4 channels/int
__device__ float g_mu[NB*NT];
__device__ float g_rstd[NB*NT];
__device__ unsigned int g_absmax[NB*NC];               // float bits, >=0
__device__ double g_beta_acc;

// ---------------- init: zero per-launch accumulators ----------------
__global__ void k_init() {
    int idx = blockIdx.x * blockDim.x + threadIdx.x;
    for (int i = idx; i < NB*NC; i += gridDim.x * blockDim.x) g_absmax[i] = 0u;
    if (idx == 0) g_beta_acc = 0.0;
}

// ---------------- sum |W| ----------------
__global__ void k_wsum(const float* __restrict__ W) {
    int tid = threadIdx.x;
    float s = 0.f;
    for (int i = blockIdx.x * blockDim.x + tid; i < NWELEM; i += gridDim.x * blockDim.x)
        s += fabsf(W[i]);
    // warp reduce
    #pragma unroll
    for (int off = 16; off; off >>= 1) s += __shfl_xor_sync(0xFFFFFFFFu, s, off);
    __shared__ float rs[8];
    if ((tid & 31) == 0) rs[tid >> 5] = s;
    __syncthreads();
    if (tid == 0) {
        float tot = 0.f;
        #pragma unroll
        for (int w = 0; w < 8; w++) tot += rs[w];
        atomicAdd(&g_beta_acc, (double)tot);
    }
}

// ---------------- quantize weights: W[o][i][k] -> g_wq [k][o][i] packed ----------------
__global__ void k_quantw(const float* __restrict__ W) {
    int idx = blockIdx.x * blockDim.x + threadIdx.x;   // over NK*NC*(NC/4) packed ints
    int total = NK * NC * (NC/4);
    if (idx >= total) return;
    float beta = fmaxf((float)(g_beta_acc * (1.0 / (double)NWELEM)), 1e-5f);
    float inv_beta = 1.f / beta;
    int k  = idx / (NC * (NC/4));
    int r  = idx % (NC * (NC/4));
    int o  = r / (NC/4);
    int i4 = r % (NC/4);
    int p = 0;
    #pragma unroll
    for (int j = 0; j < 4; j++) {
        int i = i4*4 + j;
        float ws = W[(o*NC + i)*NK + k] * inv_beta;
        ws = fminf(fmaxf(ws, -1.f), 1.f);
        int q = (int)rintf(ws);
        p |= (q & 0xFF) << (8*j);
    }
    ((int*)g_wq)[idx] = p;   // idx == k*(NC*NC/4) + o*(NC/4) + i4
}

// ---------------- layernorm stats per row (b,t) ----------------
__global__ void k_lnstats(const float* __restrict__ x) {
    int row = blockIdx.x;                       // b*NT + t
    int tid = threadIdx.x;
    const float* xr = x + (size_t)row * NC;
    float s = 0.f, s2 = 0.f;
    #pragma unroll
    for (int j = 0; j < 4; j++) {
        float v = xr[tid + j*256];
        s += v; s2 += v*v;
    }
    #pragma unroll
    for (int off = 16; off; off >>= 1) {
        s  += __shfl_xor_sync(0xFFFFFFFFu, s,  off);
        s2 += __shfl_xor_sync(0xFFFFFFFFu, s2, off);
    }
    __shared__ float rs[8], rq[8];
    if ((tid & 31) == 0) { rs[tid >> 5] = s; rq[tid >> 5] = s2; }
    __syncthreads();
    if (tid == 0) {
        float ts = 0.f, tq = 0.f;
        #pragma unroll
        for (int w = 0; w < 8; w++) { ts += rs[w]; tq += rq[w]; }
        float mu  = ts * (1.f/NC);
        float var = fmaxf(tq * (1.f/NC) - mu*mu, 0.f);
        g_mu[row]   = mu;
        g_rstd[row] = rsqrtf(var + 1e-5f);
    }
}

// ---------------- abs-max over T per (b,c) of normalized x ----------------
__global__ void k_absmax(const float* __restrict__ x,
                         const float* __restrict__ gamma,
                         const float* __restrict__ betaln) {
    int c  = blockIdx.x * blockDim.x + threadIdx.x;   // 4 blocks.x * 256
    int b  = blockIdx.z;
    int t0 = blockIdx.y * 256;                        // 16 chunks
    float gm = gamma[c], bb = betaln[c];
    const float* xp = x + ((size_t)(b*NT + t0)) * NC + c;
    const float* mup = g_mu   + b*NT + t0;
    const float* rsp = g_rstd + b*NT + t0;
    float m = 0.f;
    #pragma unroll 8
    for (int tt = 0; tt < 256; tt++) {
        float v = xp[(size_t)tt * NC];
        v = (v - mup[tt]) * rsp[tt] * gm + bb;
        m = fmaxf(m, fabsf(v));
    }
    atomicMax(&g_absmax[b*NC + c], __float_as_uint(m));
}

// ---------------- quantize + transpose x -> g_xq packed [b][ig][t] ----------------
__global__ void k_quantx(const float* __restrict__ x,
                         const float* __restrict__ gamma,
                         const float* __restrict__ betaln) {
    __shared__ signed char sq[32*36];
    int tid = threadIdx.x;
    int t0 = blockIdx.x * 32, c0 = blockIdx.y * 32, b = blockIdx.z;
    #pragma unroll
    for (int it = 0; it < 4; it++) {
        int l  = it*256 + tid;
        int tt = l >> 5, cc = l & 31;
        int t = t0 + tt, c = c0 + cc;
        int row = b*NT + t;
        float v = x[(size_t)row * NC + c];
        v = (v - g_mu[row]) * g_rstd[row] * gamma[c] + betaln[c];
        float am = fmaxf(__uint_as_float(g_absmax[b*NC + c]), 1e-5f);
        float q = rintf(v * (127.f / am));
        q = fminf(fmaxf(q, -127.f), 127.f);
        sq[cc*36 + tt] = (signed char)(int)q;
    }
    __syncthreads();
    int igl = tid >> 5, tt = tid & 31;
    int b0 = (int)sq[(igl*4+0)*36 + tt] & 0xFF;
    int b1 = (int)sq[(igl*4+1)*36 + tt] & 0xFF;
    int b2 = (int)sq[(igl*4+2)*36 + tt] & 0xFF;
    int b3 = (int)sq[(igl*4+3)*36 + tt] & 0xFF;
    int p = b0 | (b1 << 8) | (b2 << 16) | (b3 << 24);
    ((int*)g_xq)[((b*256) + (c0 >> 2) + igl) * NT + t0 + tt] = p;
}

// ---------------- conv as int8 dp4a GEMM: 128(o) x 64(t) tile ----------------
__global__ void __launch_bounds__(256)
k_conv(float* __restrict__ out) {
    __shared__ int4 As[3*128];      // [k][m] : one int4 = 16 i's of current chunk
    __shared__ int  Bs[4*68];       // [kk][tt] : tt covers t0-1 .. t0+64

    int tid = threadIdx.x;
    int tx = tid & 15, ty = tid >> 4;
    int t0 = blockIdx.x * 64;
    int o0 = blockIdx.y * 128;
    int b  = blockIdx.z;

    const int4* wq4 = (const int4*)g_wq;   // k*65536 + o*64 + chunk
    const int*  xqi = (const int*)g_xq;
    int bofs = b * 256;

    int acc[8][4];
    #pragma unroll
    for (int m = 0; m < 8; m++)
        #pragma unroll
        for (int n = 0; n < 4; n++) acc[m][n] = 0;

    for (int chunk = 0; chunk < 64; chunk++) {
        // load A: 3 k's x 128 o's, one int4 each
        #pragma unroll
        for (int l = tid; l < 384; l += 256) {
            int k = l >> 7, m = l & 127;
            As[k*128 + m] = wq4[(size_t)k*65536 + (o0 + m)*64 + chunk];
        }
        // load B: 4 kk rows x 66 t's (shifted by -1, zero padded)
        #pragma unroll
        for (int l = tid; l < 264; l += 256) {
            int kk = l / 66, tt = l % 66;
            int t = t0 - 1 + tt;
            int v = 0;
            if (t >= 0 && t < NT) v = xqi[(bofs + chunk*4 + kk)*NT + t];
            Bs[kk*68 + tt] = v;
        }
        __syncthreads();

        int bf[4][6];
        #pragma unroll
        for (int kk = 0; kk < 4; kk++)
            #pragma unroll
            for (int u = 0; u < 6; u++) bf[kk][u] = Bs[kk*68 + tx*4 + u];

        #pragma unroll
        for (int k = 0; k < 3; k++) {
            #pragma unroll
            for (int m = 0; m < 8; m++) {
                int4 a = As[k*128 + ty*8 + m];
                #pragma unroll
                for (int n = 0; n < 4; n++) {
                    acc[m][n] = __dp4a(a.x, bf[0][n+k], acc[m][n]);
                    acc[m][n] = __dp4a(a.y, bf[1][n+k], acc[m][n]);
                    acc[m][n] = __dp4a(a.z, bf[2][n+k], acc[m][n]);
                    acc[m][n] = __dp4a(a.w, bf[3][n+k], acc[m][n]);
                }
            }
        }
        __syncthreads();
    }

    // epilogue: y = acc * beta * max(absmax[b][o],eps)/127, write [b][t][o]
    float beta = fmaxf((float)(g_beta_acc * (1.0 / (double)NWELEM)), 1e-5f);
    float osc[8];
    #pragma unroll
    for (int m = 0; m < 8; m++) {
        float am = fmaxf(__uint_as_float(g_absmax[b*NC + o0 + ty*8 + m]), 1e-5f);
        osc[m] = beta * am * (1.f/127.f);
    }
    #pragma unroll
    for (int n = 0; n < 4; n++) {
        int t = t0 + tx*4 + n;
        float* op = out + ((size_t)(b*NT + t)) * NC + o0 + ty*8;
        float4 w0 = make_float4((float)acc[0][n]*osc[0], (float)acc[1][n]*osc[1],
                                (float)acc[2][n]*osc[2], (float)acc[3][n]*osc[3]);
        float4 w1 = make_float4((float)acc[4][n]*osc[4], (float)acc[5][n]*osc[5],
                                (float)acc[6][n]*osc[6], (float)acc[7][n]*osc[7]);
        ((float4*)op)[0] = w0;
        ((float4*)op)[1] = w1;
    }
}

// ---------------- launch ----------------
extern "C" void kernel_launch(void* const* d_in, const int* in_sizes, int n_in,
                              void* d_out, int out_size) {
    const float* x      = (const float*)d_in[0];   // [8,4096,1024]
    const float* gamma  = (const float*)d_in[1];   // [1024]
    const float* betaln = (const float*)d_in[2];   // [1024]
    const float* W      = (const float*)d_in[3];   // [1024,1024,3]
    float* out = (float*)d_out;

    k_init<<<32, 256>>>();
    k_wsum<<<1536, 256>>>(W);
    k_quantw<<<(NK*NC*(NC/4) + 255)/256, 256>>>(W);
    k_lnstats<<<NB*NT, 256>>>(x);
    k_absmax<<<dim3(NC/256, 16, NB), 256>>>(x, gamma, betaln);
    k_quantx<<<dim3(NT/32, NC/32, NB), 256>>>(x, gamma, betaln);
    k_conv<<<dim3(NT/64, NC/128, NB), 256>>>(out);
}

// round 2
// speedup vs baseline: 1.1893x; 1.1893x over previous
#include <cuda_runtime.h>
#include <cstdint>

#define NB 8
#define NT 4096
#define NC 1024      // C_in == C_out
#define NK 3
#define NWELEM (NK*NC*NC)   // 3145728

// ---------------- device scratch (static; no allocations) ----------------
__device__ __align__(16) signed char g_wq[NK*NC*NC];   // [k][o][i], i packed 4/int
__device__ __align__(16) signed char g_xq[NB*NC*NT];   // ints: [(b*256+ig)][t], 4 channels/int
__device__ float g_mu[NB*NT];
__device__ float g_rstd[NB*NT];
__device__ unsigned int g_absmax[NB*NC];               // float bits, >=0
__device__ double g_beta_acc;

// ---------------- init: zero per-launch accumulators ----------------
__global__ void k_init() {
    int idx = blockIdx.x * blockDim.x + threadIdx.x;
    for (int i = idx; i < NB*NC; i += gridDim.x * blockDim.x) g_absmax[i] = 0u;
    if (idx == 0) g_beta_acc = 0.0;
}

// ---------------- sum |W| ----------------
__global__ void k_wsum(const float* __restrict__ W) {
    int tid = threadIdx.x;
    float s = 0.f;
    for (int i = blockIdx.x * blockDim.x + tid; i < NWELEM; i += gridDim.x * blockDim.x)
        s += fabsf(W[i]);
    #pragma unroll
    for (int off = 16; off; off >>= 1) s += __shfl_xor_sync(0xFFFFFFFFu, s, off);
    __shared__ float rs[8];
    if ((tid & 31) == 0) rs[tid >> 5] = s;
    __syncthreads();
    if (tid == 0) {
        float tot = 0.f;
        #pragma unroll
        for (int w = 0; w < 8; w++) tot += rs[w];
        atomicAdd(&g_beta_acc, (double)tot);
    }
}

// ---------------- quantize weights: W[o][i][k] -> g_wq [k][o][i] packed ----------------
__global__ void k_quantw(const float* __restrict__ W) {
    int idx = blockIdx.x * blockDim.x + threadIdx.x;   // over NK*NC*(NC/4) packed ints
    int total = NK * NC * (NC/4);
    if (idx >= total) return;
    float beta = fmaxf((float)(g_beta_acc * (1.0 / (double)NWELEM)), 1e-5f);
    float inv_beta = 1.f / beta;
    int k  = idx / (NC * (NC/4));
    int r  = idx % (NC * (NC/4));
    int o  = r / (NC/4);
    int i4 = r % (NC/4);
    int p = 0;
    #pragma unroll
    for (int j = 0; j < 4; j++) {
        int i = i4*4 + j;
        float ws = W[(o*NC + i)*NK + k] * inv_beta;
        ws = fminf(fmaxf(ws, -1.f), 1.f);
        int q = (int)rintf(ws);
        p |= (q & 0xFF) << (8*j);
    }
    ((int*)g_wq)[idx] = p;   // idx == k*(NC*NC/4) + o*(NC/4) + i4
}

// ---------------- layernorm stats per row (b,t) ----------------
__global__ void k_lnstats(const float* __restrict__ x) {
    int row = blockIdx.x;                       // b*NT + t
    int tid = threadIdx.x;
    const float* xr = x + (size_t)row * NC;
    float s = 0.f, s2 = 0.f;
    #pragma unroll
    for (int j = 0; j < 4; j++) {
        float v = xr[tid + j*256];
        s += v; s2 += v*v;
    }
    #pragma unroll
    for (int off = 16; off; off >>= 1) {
        s  += __shfl_xor_sync(0xFFFFFFFFu, s,  off);
        s2 += __shfl_xor_sync(0xFFFFFFFFu, s2, off);
    }
    __shared__ float rs[8], rq[8];
    if ((tid & 31) == 0) { rs[tid >> 5] = s; rq[tid >> 5] = s2; }
    __syncthreads();
    if (tid == 0) {
        float ts = 0.f, tq = 0.f;
        #pragma unroll
        for (int w = 0; w < 8; w++) { ts += rs[w]; tq += rq[w]; }
        float mu  = ts * (1.f/NC);
        float var = fmaxf(tq * (1.f/NC) - mu*mu, 0.f);
        g_mu[row]   = mu;
        g_rstd[row] = rsqrtf(var + 1e-5f);
    }
}

// ---------------- abs-max over T per (b,c) of normalized x ----------------
__global__ void k_absmax(const float* __restrict__ x,
                         const float* __restrict__ gamma,
                         const float* __restrict__ betaln) {
    int c  = blockIdx.x * blockDim.x + threadIdx.x;
    int b  = blockIdx.z;
    int t0 = blockIdx.y * 256;
    float gm = gamma[c], bb = betaln[c];
    const float* xp = x + ((size_t)(b*NT + t0)) * NC + c;
    const float* mup = g_mu   + b*NT + t0;
    const float* rsp = g_rstd + b*NT + t0;
    float m = 0.f;
    #pragma unroll 8
    for (int tt = 0; tt < 256; tt++) {
        float v = xp[(size_t)tt * NC];
        v = (v - mup[tt]) * rsp[tt] * gm + bb;
        m = fmaxf(m, fabsf(v));
    }
    atomicMax(&g_absmax[b*NC + c], __float_as_uint(m));
}

// ---------------- quantize + transpose x -> g_xq packed [b][ig][t] ----------------
__global__ void k_quantx(const float* __restrict__ x,
                         const float* __restrict__ gamma,
                         const float* __restrict__ betaln) {
    __shared__ signed char sq[32*36];
    int tid = threadIdx.x;
    int t0 = blockIdx.x * 32, c0 = blockIdx.y * 32, b = blockIdx.z;
    #pragma unroll
    for (int it = 0; it < 4; it++) {
        int l  = it*256 + tid;
        int tt = l >> 5, cc = l & 31;
        int t = t0 + tt, c = c0 + cc;
        int row = b*NT + t;
        float v = x[(size_t)row * NC + c];
        v = (v - g_mu[row]) * g_rstd[row] * gamma[c] + betaln[c];
        float am = fmaxf(__uint_as_float(g_absmax[b*NC + c]), 1e-5f);
        float q = rintf(v * (127.f / am));
        q = fminf(fmaxf(q, -127.f), 127.f);
        sq[cc*36 + tt] = (signed char)(int)q;
    }
    __syncthreads();
    int igl = tid >> 5, tt = tid & 31;
    int b0 = (int)sq[(igl*4+0)*36 + tt] & 0xFF;
    int b1 = (int)sq[(igl*4+1)*36 + tt] & 0xFF;
    int b2 = (int)sq[(igl*4+2)*36 + tt] & 0xFF;
    int b3 = (int)sq[(igl*4+3)*36 + tt] & 0xFF;
    int p = b0 | (b1 << 8) | (b2 << 16) | (b3 << 24);
    ((int*)g_xq)[((b*256) + (c0 >> 2) + igl) * NT + t0 + tt] = p;
}

// ---------------- int8 tensor-core conv: 128(o) x 128(t) tile ----------------

__device__ __forceinline__ void mma_s8(int& c0, int& c1, int& c2, int& c3,
                                       int a0, int a1, int a2, int a3,
                                       int b0, int b1) {
    asm volatile("mma.sync.aligned.m16n8k32.row.col.s32.s8.s8.s32 "
                 "{%0,%1,%2,%3}, {%4,%5,%6,%7}, {%8,%9}, {%0,%1,%2,%3};"
                 : "+r"(c0), "+r"(c1), "+r"(c2), "+r"(c3)
                 : "r"(a0), "r"(a1), "r"(a2), "r"(a3), "r"(b0), "r"(b1));
}

__device__ __forceinline__ void cpa16(void* dst, const void* src) {
    uint32_t d = (uint32_t)__cvta_generic_to_shared(dst);
    asm volatile("cp.async.cg.shared.global [%0], [%1], 16;" :: "r"(d), "l"(src));
}
__device__ __forceinline__ void cpa4(void* dst, const void* src, int valid) {
    uint32_t d = (uint32_t)__cvta_generic_to_shared(dst);
    asm volatile("{\n\t"
                 ".reg .pred p;\n\t"
                 "setp.ne.u32 p, %2, 0;\n\t"
                 "@p cp.async.ca.shared.global [%0], [%1], 4;\n\t"
                 "@!p st.shared.u32 [%0], 0;\n\t"
                 "}" :: "r"(d), "l"(src), "r"(valid));
}

#define BSTRIDE 136   // ints per B smem row (conflict-free: 136 % 32 == 8)

__global__ void __launch_bounds__(256)
k_conv_mma(float* __restrict__ out) {
    __shared__ int sA[2][3*128*8];        // [buf][(k*128+row)*8 + j]   12KB each
    __shared__ int sB[2][8*BSTRIDE];      // [buf][ig*136 + col], col 0..129  4.3KB each

    int tid  = threadIdx.x;
    int lane = tid & 31, warp = tid >> 5;
    int wm = warp & 3, wn = warp >> 2;    // 4 x 2 warp grid
    int t0 = blockIdx.x * 128;
    int o0 = blockIdx.y * 128;
    int b  = blockIdx.z;

    const int* wq = (const int*)g_wq;
    const int* xq = (const int*)g_xq;

    int acc[2][8][4];
    #pragma unroll
    for (int mt = 0; mt < 2; mt++)
        #pragma unroll
        for (int nt = 0; nt < 8; nt++)
            #pragma unroll
            for (int r = 0; r < 4; r++) acc[mt][nt][r] = 0;

    int q = lane & 3, r = lane >> 2;

    // ---- async load of chunk ic into buffer buf ----
    auto issue = [&](int ic, int buf) {
        // A: 3 taps x 128 rows x 32B, int4 granularity (768 ldgsts)
        #pragma unroll
        for (int l = tid; l < 768; l += 256) {
            int k = l >> 8, rr = l & 255, row = rr >> 1, h = rr & 1;
            const int* src = wq + ((k*NC + o0 + row) << 8) + (ic << 3) + (h << 2);
            cpa16(&sA[buf][((k*128 + row) << 3) + (h << 2)], src);
        }
        // B: 8 ig rows x 130 cols (t0-1 .. t0+128), scalar w/ zero-fill at edges
        for (int l = tid; l < 1040; l += 256) {
            int igl = l / 130, c = l % 130;
            int t = t0 - 1 + c;
            const int* src = xq + ((size_t)(b*256 + (ic << 3) + igl)) * NT + t;
            cpa4(&sB[buf][igl*BSTRIDE + c], src, (t >= 0) & (t < NT));
        }
        asm volatile("cp.async.commit_group;");
    };

    issue(0, 0);

    for (int ic = 0; ic < 32; ic++) {
        int buf = ic & 1;
        if (ic < 31) issue(ic + 1, buf ^ 1);
        if (ic < 31) asm volatile("cp.async.wait_group 1;");
        else         asm volatile("cp.async.wait_group 0;");
        __syncthreads();

        const int* A = sA[buf];
        const int* B = sB[buf];

        #pragma unroll
        for (int k = 0; k < 3; k++) {
            int a[2][4];
            #pragma unroll
            for (int mt = 0; mt < 2; mt++) {
                int rb = wm*32 + mt*16;
                const int* Ak = A + (k*128 << 3);
                a[mt][0] = Ak[((rb + r)     << 3) + q];
                a[mt][1] = Ak[((rb + 8 + r) << 3) + q];
                a[mt][2] = Ak[((rb + r)     << 3) + 4 + q];
                a[mt][3] = Ak[((rb + 8 + r) << 3) + 4 + q];
            }
            #pragma unroll
            for (int nt = 0; nt < 8; nt++) {
                int col = wn*64 + nt*8 + r + k;   // sB col 0 == t0-1; output n uses t0+n+k-1
                int b0 = B[q*BSTRIDE + col];
                int b1 = B[(4 + q)*BSTRIDE + col];
                #pragma unroll
                for (int mt = 0; mt < 2; mt++)
                    mma_s8(acc[mt][nt][0], acc[mt][nt][1], acc[mt][nt][2], acc[mt][nt][3],
                           a[mt][0], a[mt][1], a[mt][2], a[mt][3], b0, b1);
            }
        }
        __syncthreads();
    }

    // ---- epilogue: y = acc * beta * max(absmax[b][o],eps)/127, write [b][t][o] ----
    float beta = fmaxf((float)(g_beta_acc * (1.0 / (double)NWELEM)), 1e-5f);
    #pragma unroll
    for (int mt = 0; mt < 2; mt++) {
        int ro = o0 + wm*32 + mt*16 + r;
        float s0 = beta * fmaxf(__uint_as_float(g_absmax[b*NC + ro]),     1e-5f) * (1.f/127.f);
        float s1 = beta * fmaxf(__uint_as_float(g_absmax[b*NC + ro + 8]), 1e-5f) * (1.f/127.f);
        #pragma unroll
        for (int nt = 0; nt < 8; nt++) {
            int t = t0 + wn*64 + nt*8 + q*2;
            float* p0 = out + ((size_t)(b*NT + t)) * NC;
            float* p1 = p0 + NC;   // t+1
            p0[ro]     = (float)acc[mt][nt][0] * s0;
            p1[ro]     = (float)acc[mt][nt][1] * s0;
            p0[ro + 8] = (float)acc[mt][nt][2] * s1;
            p1[ro + 8] = (float)acc[mt][nt][3] * s1;
        }
    }
}

// ---------------- launch ----------------
extern "C" void kernel_launch(void* const* d_in, const int* in_sizes, int n_in,
                              void* d_out, int out_size) {
    const float* x      = (const float*)d_in[0];   // [8,4096,1024]
    const float* gamma  = (const float*)d_in[1];   // [1024]
    const float* betaln = (const float*)d_in[2];   // [1024]
    const float* W      = (const float*)d_in[3];   // [1024,1024,3]
    float* out = (float*)d_out;

    k_init<<<32, 256>>>();
    k_wsum<<<1536, 256>>>(W);
    k_quantw<<<(NK*NC*(NC/4) + 255)/256, 256>>>(W);
    k_lnstats<<<NB*NT, 256>>>(x);
    k_absmax<<<dim3(NC/256, 16, NB), 256>>>(x, gamma, betaln);
    k_quantx<<<dim3(NT/32, NC/32, NB), 256>>>(x, gamma, betaln);
    k_conv_mma<<<dim3(NT/128, NC/128, NB), 256>>>(out);
}

// round 4
// speedup vs baseline: 1.2528x; 1.0533x over previous
#include <cuda_runtime.h>
#include <cstdint>

#define NB 8
#define NT 4096
#define NC 1024      // C_in == C_out
#define NK 3
#define NWELEM (NK*NC*NC)   // 3145728
#define XSTRIDE (NT + 16)   // g_xq row stride in ints (8 guard ints each side)

// ---------------- device scratch (static; no allocations) ----------------
__device__ __align__(16) signed char g_wq[NK*NC*NC];     // [k][ic(32)][o][j(8 ints)] = 32 i-chans/chunk
__device__ __align__(16) int g_xq[NB*256*XSTRIDE];       // [(b*256+ig)][8 + t], guards zeroed
__device__ float g_mu[NB*NT];
__device__ float g_rstd[NB*NT];
__device__ unsigned int g_absmax[NB*NC];                 // float bits, >=0
__device__ double g_beta_acc;

// ---------------- init: zero accumulators + g_xq guard columns ----------------
__global__ void k_init() {
    int idx = blockIdx.x * blockDim.x + threadIdx.x;
    int stride = gridDim.x * blockDim.x;
    for (int i = idx; i < NB*NC; i += stride) g_absmax[i] = 0u;
    for (int i = idx; i < NB*256*16; i += stride) {
        int row = i >> 4, g = i & 15;
        int col = (g < 8) ? g : (NT + g);     // cols 0..7 and NT+8..NT+15
        g_xq[row * XSTRIDE + col] = 0;
    }
    if (idx == 0) g_beta_acc = 0.0;
}

// ---------------- sum |W| ----------------
__global__ void k_wsum(const float* __restrict__ W) {
    int tid = threadIdx.x;
    float s = 0.f;
    for (int i = blockIdx.x * blockDim.x + tid; i < NWELEM; i += gridDim.x * blockDim.x)
        s += fabsf(W[i]);
    #pragma unroll
    for (int off = 16; off; off >>= 1) s += __shfl_xor_sync(0xFFFFFFFFu, s, off);
    __shared__ float rs[8];
    if ((tid & 31) == 0) rs[tid >> 5] = s;
    __syncthreads();
    if (tid == 0) {
        float tot = 0.f;
        #pragma unroll
        for (int w = 0; w < 8; w++) tot += rs[w];
        atomicAdd(&g_beta_acc, (double)tot);
    }
}

// ---------------- quantize weights: W[o][i][k] -> g_wq [k][ic][o][j] packed ----------------
__global__ void k_quantw(const float* __restrict__ W) {
    int idx = blockIdx.x * blockDim.x + threadIdx.x;   // over NK*NC*(NC/4) packed ints
    int total = NK * NC * (NC/4);
    if (idx >= total) return;
    float beta = fmaxf((float)(g_beta_acc * (1.0 / (double)NWELEM)), 1e-5f);
    float inv_beta = 1.f / beta;
    int k  = idx / (NC * (NC/4));
    int r  = idx % (NC * (NC/4));
    int o  = r / (NC/4);
    int i4 = r % (NC/4);
    int p = 0;
    #pragma unroll
    for (int j = 0; j < 4; j++) {
        int i = i4*4 + j;
        float ws = W[(o*NC + i)*NK + k] * inv_beta;
        ws = fminf(fmaxf(ws, -1.f), 1.f);
        int q = (int)rintf(ws);
        p |= (q & 0xFF) << (8*j);
    }
    int ic = i4 >> 3, j8 = i4 & 7;                     // ic in 0..31
    ((int*)g_wq)[((k*32 + ic)*NC + o)*8 + j8] = p;
}

// ---------------- layernorm stats per row (b,t) ----------------
__global__ void k_lnstats(const float* __restrict__ x) {
    int row = blockIdx.x;                       // b*NT + t
    int tid = threadIdx.x;
    const float* xr = x + (size_t)row * NC;
    float s = 0.f, s2 = 0.f;
    #pragma unroll
    for (int j = 0; j < 4; j++) {
        float v = xr[tid + j*256];
        s += v; s2 += v*v;
    }
    #pragma unroll
    for (int off = 16; off; off >>= 1) {
        s  += __shfl_xor_sync(0xFFFFFFFFu, s,  off);
        s2 += __shfl_xor_sync(0xFFFFFFFFu, s2, off);
    }
    __shared__ float rs[8], rq[8];
    if ((tid & 31) == 0) { rs[tid >> 5] = s; rq[tid >> 5] = s2; }
    __syncthreads();
    if (tid == 0) {
        float ts = 0.f, tq = 0.f;
        #pragma unroll
        for (int w = 0; w < 8; w++) { ts += rs[w]; tq += rq[w]; }
        float mu  = ts * (1.f/NC);
        float var = fmaxf(tq * (1.f/NC) - mu*mu, 0.f);
        g_mu[row]   = mu;
        g_rstd[row] = rsqrtf(var + 1e-5f);
    }
}

// ---------------- abs-max over T per (b,c) of normalized x ----------------
__global__ void k_absmax(const float* __restrict__ x,
                         const float* __restrict__ gamma,
                         const float* __restrict__ betaln) {
    int c  = blockIdx.x * blockDim.x + threadIdx.x;
    int b  = blockIdx.z;
    int t0 = blockIdx.y * 256;
    float gm = gamma[c], bb = betaln[c];
    const float* xp = x + ((size_t)(b*NT + t0)) * NC + c;
    const float* mup = g_mu   + b*NT + t0;
    const float* rsp = g_rstd + b*NT + t0;
    float m = 0.f;
    #pragma unroll 8
    for (int tt = 0; tt < 256; tt++) {
        float v = xp[(size_t)tt * NC];
        v = (v - mup[tt]) * rsp[tt] * gm + bb;
        m = fmaxf(m, fabsf(v));
    }
    atomicMax(&g_absmax[b*NC + c], __float_as_uint(m));
}

// ---------------- quantize + transpose x -> g_xq packed [b][ig][8+t] ----------------
__global__ void k_quantx(const float* __restrict__ x,
                         const float* __restrict__ gamma,
                         const float* __restrict__ betaln) {
    __shared__ signed char sq[32*36];
    int tid = threadIdx.x;
    int t0 = blockIdx.x * 32, c0 = blockIdx.y * 32, b = blockIdx.z;
    #pragma unroll
    for (int it = 0; it < 4; it++) {
        int l  = it*256 + tid;
        int tt = l >> 5, cc = l & 31;
        int t = t0 + tt, c = c0 + cc;
        int row = b*NT + t;
        float v = x[(size_t)row * NC + c];
        v = (v - g_mu[row]) * g_rstd[row] * gamma[c] + betaln[c];
        float am = fmaxf(__uint_as_float(g_absmax[b*NC + c]), 1e-5f);
        float q = rintf(v * (127.f / am));
        q = fminf(fmaxf(q, -127.f), 127.f);
        sq[cc*36 + tt] = (signed char)(int)q;
    }
    __syncthreads();
    int igl = tid >> 5, tt = tid & 31;
    int b0 = (int)sq[(igl*4+0)*36 + tt] & 0xFF;
    int b1 = (int)sq[(igl*4+1)*36 + tt] & 0xFF;
    int b2 = (int)sq[(igl*4+2)*36 + tt] & 0xFF;
    int b3 = (int)sq[(igl*4+3)*36 + tt] & 0xFF;
    int p = b0 | (b1 << 8) | (b2 << 16) | (b3 << 24);
    g_xq[((b*256) + (c0 >> 2) + igl) * XSTRIDE + 8 + t0 + tt] = p;
}

// ---------------- int8 tensor-core conv: 128(o) x 128(t) tile, bulk-copy pipeline ----------------

__device__ __forceinline__ void mma_s8(int& c0, int& c1, int& c2, int& c3,
                                       int a0, int a1, int a2, int a3,
                                       int b0, int b1) {
    asm volatile("mma.sync.aligned.m16n8k32.row.col.s32.s8.s8.s32 "
                 "{%0,%1,%2,%3}, {%4,%5,%6,%7}, {%8,%9}, {%0,%1,%2,%3};"
                 : "+r"(c0), "+r"(c1), "+r"(c2), "+r"(c3)
                 : "r"(a0), "r"(a1), "r"(a2), "r"(a3), "r"(b0), "r"(b1));
}

__device__ __forceinline__ void bulk_g2s(uint32_t dst, const void* src, uint32_t bytes, uint32_t mbar) {
    asm volatile("cp.async.bulk.shared::cta.global.mbarrier::complete_tx::bytes "
                 "[%0], [%1], %2, [%3];"
                 :: "r"(dst), "l"(src), "r"(bytes), "r"(mbar) : "memory");
}
__device__ __forceinline__ void mbar_init(uint32_t mbar, uint32_t count) {
    asm volatile("mbarrier.init.shared.b64 [%0], %1;" :: "r"(mbar), "r"(count) : "memory");
}
__device__ __forceinline__ void mbar_expect_tx(uint32_t mbar, uint32_t bytes) {
    asm volatile("mbarrier.arrive.expect_tx.shared.b64 _, [%0], %1;" :: "r"(mbar), "r"(bytes) : "memory");
}
__device__ __forceinline__ void mbar_wait(uint32_t mbar, uint32_t parity) {
    asm volatile("{\n\t"
                 ".reg .pred P;\n\t"
                 "WL_%=:\n\t"
                 "mbarrier.try_wait.parity.acquire.cta.shared::cta.b64 P, [%0], %1, 0x989680;\n\t"
                 "@P bra WD_%=;\n\t"
                 "bra WL_%=;\n\t"
                 "WD_%=:\n\t"
                 "}" :: "r"(mbar), "r"(parity) : "memory");
}

#define BSTRIDE 152                  // ints per B smem row (bank map (24q+r)%32 conflict-free)
#define CHUNK_BYTES (3*4096 + 8*576) // 16896

__global__ void __launch_bounds__(256)
k_conv_mma(float* __restrict__ out) {
    __shared__ __align__(16) int sA[2][3*128*8];      // [buf][(k*128+row)*8 + j]   12KB each
    __shared__ __align__(16) int sB[2][8*BSTRIDE];    // [buf][ig*152 + col], col 0..143
    __shared__ __align__(8)  unsigned long long mbar[2];

    int tid  = threadIdx.x;
    int lane = tid & 31, warp = tid >> 5;
    int wm = warp & 3, wn = warp >> 2;    // 4 x 2 warp grid; warp tile 32(o) x 64(t)
    int t0 = blockIdx.x * 128;
    int o0 = blockIdx.y * 128;
    int b  = blockIdx.z;

    const char* wqb = (const char*)g_wq;
    const int*  xq  = g_xq;

    uint32_t sA0 = (uint32_t)__cvta_generic_to_shared(&sA[0][0]);
    uint32_t sA1 = (uint32_t)__cvta_generic_to_shared(&sA[1][0]);
    uint32_t sB0 = (uint32_t)__cvta_generic_to_shared(&sB[0][0]);
    uint32_t sB1 = (uint32_t)__cvta_generic_to_shared(&sB[1][0]);
    uint32_t mb0 = (uint32_t)__cvta_generic_to_shared(&mbar[0]);
    uint32_t mb1 = (uint32_t)__cvta_generic_to_shared(&mbar[1]);

    if (tid == 0) { mbar_init(mb0, 1); mbar_init(mb1, 1); }
    __syncthreads();

    // issue chunk ic into buffer buf (thread 0 only)
    auto issue = [&](int ic, int buf) {
        uint32_t mb = buf ? mb1 : mb0;
        uint32_t dA = buf ? sA1 : sA0;
        uint32_t dB = buf ? sB1 : sB0;
        mbar_expect_tx(mb, CHUNK_BYTES);
        #pragma unroll
        for (int k = 0; k < 3; k++) {
            const void* src = wqb + ((size_t)((k*32 + ic)*NC + o0) << 5);  // *32 bytes
            bulk_g2s(dA + k*4096, src, 4096, mb);
        }
        #pragma unroll
        for (int ig = 0; ig < 8; ig++) {
            const void* src = xq + (size_t)(b*256 + ic*8 + ig) * XSTRIDE + t0;  // covers t0-8..t0+135
            bulk_g2s(dB + ig*(BSTRIDE*4), src, 576, mb);
        }
    };

    int acc[2][8][4];
    #pragma unroll
    for (int mt = 0; mt < 2; mt++)
        #pragma unroll
        for (int nt = 0; nt < 8; nt++)
            #pragma unroll
            for (int rr = 0; rr < 4; rr++) acc[mt][nt][rr] = 0;

    int q = lane & 3, r = lane >> 2;

    if (tid == 0) issue(0, 0);

    for (int ic = 0; ic < 32; ic++) {
        int buf = ic & 1;
        if (ic < 31 && tid == 0) issue(ic + 1, buf ^ 1);
        mbar_wait(buf ? mb1 : mb0, (ic >> 1) & 1);

        const int* A = sA[buf];
        const int* B = sB[buf];

        #pragma unroll
        for (int k = 0; k < 3; k++) {
            int a[2][4];
            #pragma unroll
            for (int mt = 0; mt < 2; mt++) {
                int rb = wm*32 + mt*16;
                const int* Ak = A + (k << 10);
                a[mt][0] = Ak[((rb + r)     << 3) + q];
                a[mt][1] = Ak[((rb + 8 + r) << 3) + q];
                a[mt][2] = Ak[((rb + r)     << 3) + 4 + q];
                a[mt][3] = Ak[((rb + 8 + r) << 3) + 4 + q];
            }
            #pragma unroll
            for (int nt = 0; nt < 8; nt++) {
                int col = wn*64 + nt*8 + r + k + 7;   // sB col 0 == t0-8; t = t0+n+k-1
                int b0 = B[q*BSTRIDE + col];
                int b1 = B[(4 + q)*BSTRIDE + col];
                #pragma unroll
                for (int mt = 0; mt < 2; mt++)
                    mma_s8(acc[mt][nt][0], acc[mt][nt][1], acc[mt][nt][2], acc[mt][nt][3],
                           a[mt][0], a[mt][1], a[mt][2], a[mt][3], b0, b1);
            }
        }
        __syncthreads();
    }

    // ---- epilogue: y = acc * beta * max(absmax[b][o],eps)/127, write [b][t][o] ----
    float beta = fmaxf((float)(g_beta_acc * (1.0 / (double)NWELEM)), 1e-5f);
    #pragma unroll
    for (int mt = 0; mt < 2; mt++) {
        int ro = o0 + wm*32 + mt*16 + r;
        float s0 = beta * fmaxf(__uint_as_float(g_absmax[b*NC + ro]),     1e-5f) * (1.f/127.f);
        float s1 = beta * fmaxf(__uint_as_float(g_absmax[b*NC + ro + 8]), 1e-5f) * (1.f/127.f);
        #pragma unroll
        for (int nt = 0; nt < 8; nt++) {
            int t = t0 + wn*64 + nt*8 + q*2;
            float* p0 = out + ((size_t)(b*NT + t)) * NC;
            float* p1 = p0 + NC;   // t+1
            p0[ro]     = (float)acc[mt][nt][0] * s0;
            p1[ro]     = (float)acc[mt][nt][1] * s0;
            p0[ro + 8] = (float)acc[mt][nt][2] * s1;
            p1[ro + 8] = (float)acc[mt][nt][3] * s1;
        }
    }
}

// ---------------- launch ----------------
extern "C" void kernel_launch(void* const* d_in, const int* in_sizes, int n_in,
                              void* d_out, int out_size) {
    const float* x      = (const float*)d_in[0];   // [8,4096,1024]
    const float* gamma  = (const float*)d_in[1];   // [1024]
    const float* betaln = (const float*)d_in[2];   // [1024]
    const float* W      = (const float*)d_in[3];   // [1024,1024,3]
    float* out = (float*)d_out;

    k_init<<<64, 256>>>();
    k_wsum<<<1536, 256>>>(W);
    k_quantw<<<(NK*NC*(NC/4) + 255)/256, 256>>>(W);
    k_lnstats<<<NB*NT, 256>>>(x);
    k_absmax<<<dim3(NC/256, 16, NB), 256>>>(x, gamma, betaln);
    k_quantx<<<dim3(NT/32, NC/32, NB), 256>>>(x, gamma, betaln);
    k_conv_mma<<<dim3(NT/128, NC/128, NB), 256>>>(out);
}

// round 6
// speedup vs baseline: 1.3899x; 1.1094x over previous
#include <cuda_runtime.h>
#include <cstdint>

#define NB 8
#define NT 4096
#define NC 1024      // C_in == C_out
#define NK 3
#define NWELEM (NK*NC*NC)   // 3145728
#define XSTRIDE (NT + 16)   // g_xq row stride in ints (8 guard ints each side)

#define Y_IMMA 5            // o-tiles 0..4 -> IMMA path; 5..7 -> dp4a path

// ---------------- device scratch (static; no allocations) ----------------
__device__ __align__(16) signed char g_wq[NK*NC*NC];     // [k][ic(32)][o][j(8 ints)] = 32 i-chans/chunk
__device__ __align__(16) int g_xq[NB*256*XSTRIDE];       // [(b*256+ig)][8 + t], guards zeroed
__device__ float g_mu[NB*NT];
__device__ float g_rstd[NB*NT];
__device__ unsigned int g_absmax[NB*NC];                 // float bits, >=0
__device__ double g_beta_acc;

// ---------------- init: zero accumulators + g_xq guard columns ----------------
__global__ void k_init() {
    int idx = blockIdx.x * blockDim.x + threadIdx.x;
    int stride = gridDim.x * blockDim.x;
    for (int i = idx; i < NB*NC; i += stride) g_absmax[i] = 0u;
    for (int i = idx; i < NB*256*16; i += stride) {
        int row = i >> 4, g = i & 15;
        int col = (g < 8) ? g : (NT + g);     // cols 0..7 and NT+8..NT+15
        g_xq[row * XSTRIDE + col] = 0;
    }
    if (idx == 0) g_beta_acc = 0.0;
}

// ---------------- sum |W| ----------------
__global__ void k_wsum(const float* __restrict__ W) {
    int tid = threadIdx.x;
    float s = 0.f;
    for (int i = blockIdx.x * blockDim.x + tid; i < NWELEM; i += gridDim.x * blockDim.x)
        s += fabsf(W[i]);
    #pragma unroll
    for (int off = 16; off; off >>= 1) s += __shfl_xor_sync(0xFFFFFFFFu, s, off);
    __shared__ float rs[8];
    if ((tid & 31) == 0) rs[tid >> 5] = s;
    __syncthreads();
    if (tid == 0) {
        float tot = 0.f;
        #pragma unroll
        for (int w = 0; w < 8; w++) tot += rs[w];
        atomicAdd(&g_beta_acc, (double)tot);
    }
}

// ---------------- quantize weights: W[o][i][k] -> g_wq [k][ic][o][j] packed ----------------
__global__ void k_quantw(const float* __restrict__ W) {
    int idx = blockIdx.x * blockDim.x + threadIdx.x;
    int total = NK * NC * (NC/4);
    if (idx >= total) return;
    float beta = fmaxf((float)(g_beta_acc * (1.0 / (double)NWELEM)), 1e-5f);
    float inv_beta = 1.f / beta;
    int k  = idx / (NC * (NC/4));
    int r  = idx % (NC * (NC/4));
    int o  = r / (NC/4);
    int i4 = r % (NC/4);
    int p = 0;
    #pragma unroll
    for (int j = 0; j < 4; j++) {
        int i = i4*4 + j;
        float ws = W[(o*NC + i)*NK + k] * inv_beta;
        ws = fminf(fmaxf(ws, -1.f), 1.f);
        int q = (int)rintf(ws);
        p |= (q & 0xFF) << (8*j);
    }
    int ic = i4 >> 3, j8 = i4 & 7;                     // ic in 0..31
    ((int*)g_wq)[((k*32 + ic)*NC + o)*8 + j8] = p;
}

// ---------------- layernorm stats per row (b,t) ----------------
__global__ void k_lnstats(const float* __restrict__ x) {
    int row = blockIdx.x;
    int tid = threadIdx.x;
    const float* xr = x + (size_t)row * NC;
    float s = 0.f, s2 = 0.f;
    #pragma unroll
    for (int j = 0; j < 4; j++) {
        float v = xr[tid + j*256];
        s += v; s2 += v*v;
    }
    #pragma unroll
    for (int off = 16; off; off >>= 1) {
        s  += __shfl_xor_sync(0xFFFFFFFFu, s,  off);
        s2 += __shfl_xor_sync(0xFFFFFFFFu, s2, off);
    }
    __shared__ float rs[8], rq[8];
    if ((tid & 31) == 0) { rs[tid >> 5] = s; rq[tid >> 5] = s2; }
    __syncthreads();
    if (tid == 0) {
        float ts = 0.f, tq = 0.f;
        #pragma unroll
        for (int w = 0; w < 8; w++) { ts += rs[w]; tq += rq[w]; }
        float mu  = ts * (1.f/NC);
        float var = fmaxf(tq * (1.f/NC) - mu*mu, 0.f);
        g_mu[row]   = mu;
        g_rstd[row] = rsqrtf(var + 1e-5f);
    }
}

// ---------------- abs-max over T per (b,c) of normalized x ----------------
__global__ void k_absmax(const float* __restrict__ x,
                         const float* __restrict__ gamma,
                         const float* __restrict__ betaln) {
    int c  = blockIdx.x * blockDim.x + threadIdx.x;
    int b  = blockIdx.z;
    int t0 = blockIdx.y * 256;
    float gm = gamma[c], bb = betaln[c];
    const float* xp = x + ((size_t)(b*NT + t0)) * NC + c;
    const float* mup = g_mu   + b*NT + t0;
    const float* rsp = g_rstd + b*NT + t0;
    float m = 0.f;
    #pragma unroll 8
    for (int tt = 0; tt < 256; tt++) {
        float v = xp[(size_t)tt * NC];
        v = (v - mup[tt]) * rsp[tt] * gm + bb;
        m = fmaxf(m, fabsf(v));
    }
    atomicMax(&g_absmax[b*NC + c], __float_as_uint(m));
}

// ---------------- quantize + transpose x -> g_xq packed [b][ig][8+t] ----------------
__global__ void k_quantx(const float* __restrict__ x,
                         const float* __restrict__ gamma,
                         const float* __restrict__ betaln) {
    __shared__ signed char sq[32*36];
    int tid = threadIdx.x;
    int t0 = blockIdx.x * 32, c0 = blockIdx.y * 32, b = blockIdx.z;
    #pragma unroll
    for (int it = 0; it < 4; it++) {
        int l  = it*256 + tid;
        int tt = l >> 5, cc = l & 31;
        int t = t0 + tt, c = c0 + cc;
        int row = b*NT + t;
        float v = x[(size_t)row * NC + c];
        v = (v - g_mu[row]) * g_rstd[row] * gamma[c] + betaln[c];
        float am = fmaxf(__uint_as_float(g_absmax[b*NC + c]), 1e-5f);
        float q = rintf(v * (127.f / am));
        q = fminf(fmaxf(q, -127.f), 127.f);
        sq[cc*36 + tt] = (signed char)(int)q;
    }
    __syncthreads();
    int igl = tid >> 5, tt = tid & 31;
    int b0 = (int)sq[(igl*4+0)*36 + tt] & 0xFF;
    int b1 = (int)sq[(igl*4+1)*36 + tt] & 0xFF;
    int b2 = (int)sq[(igl*4+2)*36 + tt] & 0xFF;
    int b3 = (int)sq[(igl*4+3)*36 + tt] & 0xFF;
    int p = b0 | (b1 << 8) | (b2 << 16) | (b3 << 24);
    g_xq[((b*256) + (c0 >> 2) + igl) * XSTRIDE + 8 + t0 + tt] = p;
}

// ---------------- hybrid conv: IMMA CTAs (y<Y_IMMA) + dp4a CTAs (y>=Y_IMMA) ----------------

__device__ __forceinline__ void mma_s8(int& c0, int& c1, int& c2, int& c3,
                                       int a0, int a1, int a2, int a3,
                                       int b0, int b1) {
    asm volatile("mma.sync.aligned.m16n8k32.row.col.s32.s8.s8.s32 "
                 "{%0,%1,%2,%3}, {%4,%5,%6,%7}, {%8,%9}, {%0,%1,%2,%3};"
                 : "+r"(c0), "+r"(c1), "+r"(c2), "+r"(c3)
                 : "r"(a0), "r"(a1), "r"(a2), "r"(a3), "r"(b0), "r"(b1));
}
__device__ __forceinline__ void bulk_g2s(uint32_t dst, const void* src, uint32_t bytes, uint32_t mbar) {
    asm volatile("cp.async.bulk.shared::cta.global.mbarrier::complete_tx::bytes "
                 "[%0], [%1], %2, [%3];"
                 :: "r"(dst), "l"(src), "r"(bytes), "r"(mbar) : "memory");
}
__device__ __forceinline__ void mbar_init(uint32_t mbar, uint32_t count) {
    asm volatile("mbarrier.init.shared.b64 [%0], %1;" :: "r"(mbar), "r"(count) : "memory");
}
__device__ __forceinline__ void mbar_expect_tx(uint32_t mbar, uint32_t bytes) {
    asm volatile("mbarrier.arrive.expect_tx.shared.b64 _, [%0], %1;" :: "r"(mbar), "r"(bytes) : "memory");
}
__device__ __forceinline__ void mbar_wait(uint32_t mbar, uint32_t parity) {
    asm volatile("{\n\t"
                 ".reg .pred P;\n\t"
                 "WL_%=:\n\t"
                 "mbarrier.try_wait.parity.acquire.cta.shared::cta.b64 P, [%0], %1, 0x989680;\n\t"
                 "@P bra WD_%=;\n\t"
                 "bra WL_%=;\n\t"
                 "WD_%=:\n\t"
                 "}" :: "r"(mbar), "r"(parity) : "memory");
}

#define BSTRIDE 152                  // ints per IMMA B smem row
#define CHUNK_TX (3*4096 + 8*576)    // 16896

__global__ void __launch_bounds__(256)
k_conv_hybrid(float* __restrict__ out) {
    // raw shared: IMMA uses [0,24576) A bufs, [24576,34304) B bufs; dp4a uses [0,7232)
    __shared__ __align__(16) char s_raw[34304];
    __shared__ __align__(8)  unsigned long long s_mbar[2];

    int tid  = threadIdx.x;
    int lane = tid & 31, warp = tid >> 5;
    int o0 = blockIdx.y * 128;
    int b  = blockIdx.z;

    float beta = fmaxf((float)(g_beta_acc * (1.0 / (double)NWELEM)), 1e-5f);

    if (blockIdx.y < Y_IMMA) {
        // ================= IMMA path (round-4, proven) =================
        int wm = warp & 3, wn = warp >> 2;
        int t0 = blockIdx.x * 128;
        const char* wqb = (const char*)g_wq;
        const int*  xq  = g_xq;

        uint32_t raw_u = (uint32_t)__cvta_generic_to_shared(s_raw);
        uint32_t mb0 = (uint32_t)__cvta_generic_to_shared(&s_mbar[0]);
        uint32_t mb1 = (uint32_t)__cvta_generic_to_shared(&s_mbar[1]);

        if (tid == 0) { mbar_init(mb0, 1); mbar_init(mb1, 1); }
        __syncthreads();

        auto issue = [&](int ic, int buf) {
            uint32_t mb = buf ? mb1 : mb0;
            uint32_t dA = raw_u + buf*12288;
            uint32_t dB = raw_u + 24576 + buf*4864;
            mbar_expect_tx(mb, CHUNK_TX);
            #pragma unroll
            for (int k = 0; k < 3; k++) {
                const void* src = wqb + ((size_t)((k*32 + ic)*NC + o0) << 5);
                bulk_g2s(dA + k*4096, src, 4096, mb);
            }
            #pragma unroll
            for (int ig = 0; ig < 8; ig++) {
                const void* src = xq + (size_t)(b*256 + ic*8 + ig) * XSTRIDE + t0;
                bulk_g2s(dB + ig*(BSTRIDE*4), src, 576, mb);
            }
        };

        int acc[2][8][4];
        #pragma unroll
        for (int mt = 0; mt < 2; mt++)
            #pragma unroll
            for (int nt = 0; nt < 8; nt++)
                #pragma unroll
                for (int rr = 0; rr < 4; rr++) acc[mt][nt][rr] = 0;

        int q = lane & 3, r = lane >> 2;

        if (tid == 0) issue(0, 0);

        for (int ic = 0; ic < 32; ic++) {
            int buf = ic & 1;
            if (ic < 31 && tid == 0) issue(ic + 1, buf ^ 1);
            mbar_wait(buf ? mb1 : mb0, (ic >> 1) & 1);

            const int* A = (const int*)s_raw + buf*3072;
            const int* B = (const int*)(s_raw + 24576) + buf*1216;

            #pragma unroll
            for (int k = 0; k < 3; k++) {
                int a[2][4];
                #pragma unroll
                for (int mt = 0; mt < 2; mt++) {
                    int rb = wm*32 + mt*16;
                    const int* Ak = A + (k << 10);
                    a[mt][0] = Ak[((rb + r)     << 3) + q];
                    a[mt][1] = Ak[((rb + 8 + r) << 3) + q];
                    a[mt][2] = Ak[((rb + r)     << 3) + 4 + q];
                    a[mt][3] = Ak[((rb + 8 + r) << 3) + 4 + q];
                }
                #pragma unroll
                for (int nt = 0; nt < 8; nt++) {
                    int col = wn*64 + nt*8 + r + k + 7;   // sB col 0 == t0-8
                    int b0 = B[q*BSTRIDE + col];
                    int b1 = B[(4 + q)*BSTRIDE + col];
                    #pragma unroll
                    for (int mt = 0; mt < 2; mt++)
                        mma_s8(acc[mt][nt][0], acc[mt][nt][1], acc[mt][nt][2], acc[mt][nt][3],
                               a[mt][0], a[mt][1], a[mt][2], a[mt][3], b0, b1);
                }
            }
            __syncthreads();
        }

        #pragma unroll
        for (int mt = 0; mt < 2; mt++) {
            int ro = o0 + wm*32 + mt*16 + r;
            float s0 = beta * fmaxf(__uint_as_float(g_absmax[b*NC + ro]),     1e-5f) * (1.f/127.f);
            float s1 = beta * fmaxf(__uint_as_float(g_absmax[b*NC + ro + 8]), 1e-5f) * (1.f/127.f);
            #pragma unroll
            for (int nt = 0; nt < 8; nt++) {
                int t = t0 + wn*64 + nt*8 + q*2;
                float* p0 = out + ((size_t)(b*NT + t)) * NC;
                float* p1 = p0 + NC;
                p0[ro]     = (float)acc[mt][nt][0] * s0;
                p1[ro]     = (float)acc[mt][nt][1] * s0;
                p0[ro + 8] = (float)acc[mt][nt][2] * s1;
                p1[ro + 8] = (float)acc[mt][nt][3] * s1;
            }
        }
    } else {
        // ================= dp4a path (round-1, proven; re-indexed) =================
        int4* As = (int4*)s_raw;                 // [k][m] 3*128 int4
        int*  Bs = (int*)(s_raw + 6144);         // [kk][tt] 4*68 ints

        int tx = tid & 15, ty = tid >> 4;
        const int4* wq4 = (const int4*)g_wq;
        const int*  xqi = g_xq;
        int bofs = b * 256;

        #pragma unroll 1
        for (int half = 0; half < 2; half++) {
            int t0 = blockIdx.x * 128 + half * 64;

            int acc[8][4];
            #pragma unroll
            for (int m = 0; m < 8; m++)
                #pragma unroll
                for (int n = 0; n < 4; n++) acc[m][n] = 0;

            for (int c = 0; c < 64; c++) {       // 16-chan chunks
                int ic = c >> 1, h = c & 1;
                #pragma unroll
                for (int l = tid; l < 384; l += 256) {
                    int k = l >> 7, m = l & 127;
                    As[k*128 + m] = wq4[((size_t)((k*32 + ic)*NC) + o0 + m)*2 + h];
                }
                #pragma unroll
                for (int l = tid; l < 264; l += 256) {
                    int kk = l / 66, tt = l % 66;
                    // padded col 7 + t0 + tt covers t = t0-1 .. t0+64 (guards absorb edges)
                    Bs[kk*68 + tt] = xqi[(size_t)(bofs + c*4 + kk)*XSTRIDE + 7 + t0 + tt];
                }
                __syncthreads();

                int bf[4][6];
                #pragma unroll
                for (int kk = 0; kk < 4; kk++)
                    #pragma unroll
                    for (int u = 0; u < 6; u++) bf[kk][u] = Bs[kk*68 + tx*4 + u];

                #pragma unroll
                for (int k = 0; k < 3; k++) {
                    #pragma unroll
                    for (int m = 0; m < 8; m++) {
                        int4 a = As[k*128 + ty*8 + m];
                        #pragma unroll
                        for (int n = 0; n < 4; n++) {
                            acc[m][n] = __dp4a(a.x, bf[0][n+k], acc[m][n]);
                            acc[m][n] = __dp4a(a.y, bf[1][n+k], acc[m][n]);
                            acc[m][n] = __dp4a(a.z, bf[2][n+k], acc[m][n]);
                            acc[m][n] = __dp4a(a.w, bf[3][n+k], acc[m][n]);
                        }
                    }
                }
                __syncthreads();
            }

            float osc[8];
            #pragma unroll
            for (int m = 0; m < 8; m++) {
                float am = fmaxf(__uint_as_float(g_absmax[b*NC + o0 + ty*8 + m]), 1e-5f);
                osc[m] = beta * am * (1.f/127.f);
            }
            #pragma unroll
            for (int n = 0; n < 4; n++) {
                int t = t0 + tx*4 + n;
                float* op = out + ((size_t)(b*NT + t)) * NC + o0 + ty*8;
                float4 w0 = make_float4((float)acc[0][n]*osc[0], (float)acc[1][n]*osc[1],
                                        (float)acc[2][n]*osc[2], (float)acc[3][n]*osc[3]);
                float4 w1 = make_float4((float)acc[4][n]*osc[4], (float)acc[5][n]*osc[5],
                                        (float)acc[6][n]*osc[6], (float)acc[7][n]*osc[7]);
                ((float4*)op)[0] = w0;
                ((float4*)op)[1] = w1;
            }
        }
    }
}

// ---------------- launch ----------------
extern "C" void kernel_launch(void* const* d_in, const int* in_sizes, int n_in,
                              void* d_out, int out_size) {
    const float* x      = (const float*)d_in[0];   // [8,4096,1024]
    const float* gamma  = (const float*)d_in[1];   // [1024]
    const float* betaln = (const float*)d_in[2];   // [1024]
    const float* W      = (const float*)d_in[3];   // [1024,1024,3]
    float* out = (float*)d_out;

    k_init<<<64, 256>>>();
    k_wsum<<<1536, 256>>>(W);
    k_quantw<<<(NK*NC*(NC/4) + 255)/256, 256>>>(W);
    k_lnstats<<<NB*NT, 256>>>(x);
    k_absmax<<<dim3(NC/256, 16, NB), 256>>>(x, gamma, betaln);
    k_quantx<<<dim3(NT/32, NC/32, NB), 256>>>(x, gamma, betaln);
    k_conv_hybrid<<<dim3(NT/128, NC/128, NB), 256>>>(out);
}

// round 7
// speedup vs baseline: 1.8545x; 1.3343x over previous
#include <cuda_runtime.h>
#include <cstdint>

#define NB 8
#define NT 4096
#define NC 1024      // C_in == C_out
#define NK 3
#define NWELEM (NK*NC*NC)   // 3145728
#define XSTRIDE (NT + 16)   // g_xq row stride in ints (8 guard ints each side)

// ---------------- device scratch (static; no allocations) ----------------
__device__ __align__(16) signed char g_wq[NK*NC*NC];     // [k][ic(32)][o][j(8 ints)] = 32 i-chans/chunk
__device__ __align__(16) int g_xq[NB*256*XSTRIDE];       // [(b*256+ig)][8 + t], guards zeroed
__device__ float g_mu[NB*NT];
__device__ float g_rstd[NB*NT];
__device__ unsigned int g_absmax[NB*NC];                 // float bits, >=0
__device__ double g_beta_acc;

// ---------------- init: zero accumulators + g_xq guard columns ----------------
__global__ void k_init() {
    int idx = blockIdx.x * blockDim.x + threadIdx.x;
    int stride = gridDim.x * blockDim.x;
    for (int i = idx; i < NB*NC; i += stride) g_absmax[i] = 0u;
    for (int i = idx; i < NB*256*16; i += stride) {
        int row = i >> 4, g = i & 15;
        int col = (g < 8) ? g : (NT + g);     // cols 0..7 and NT+8..NT+15
        g_xq[row * XSTRIDE + col] = 0;
    }
    if (idx == 0) g_beta_acc = 0.0;
}

// ---------------- sum |W| ----------------
__global__ void k_wsum(const float* __restrict__ W) {
    int tid = threadIdx.x;
    float s = 0.f;
    for (int i = blockIdx.x * blockDim.x + tid; i < NWELEM; i += gridDim.x * blockDim.x)
        s += fabsf(W[i]);
    #pragma unroll
    for (int off = 16; off; off >>= 1) s += __shfl_xor_sync(0xFFFFFFFFu, s, off);
    __shared__ float rs[8];
    if ((tid & 31) == 0) rs[tid >> 5] = s;
    __syncthreads();
    if (tid == 0) {
        float tot = 0.f;
        #pragma unroll
        for (int w = 0; w < 8; w++) tot += rs[w];
        atomicAdd(&g_beta_acc, (double)tot);
    }
}

// ---------------- quantize weights: W[o][i][k] -> g_wq [k][ic][o][j] packed ----------------
__global__ void k_quantw(const float* __restrict__ W) {
    int idx = blockIdx.x * blockDim.x + threadIdx.x;
    int total = NK * NC * (NC/4);
    if (idx >= total) return;
    float beta = fmaxf((float)(g_beta_acc * (1.0 / (double)NWELEM)), 1e-5f);
    float inv_beta = 1.f / beta;
    int k  = idx / (NC * (NC/4));
    int r  = idx % (NC * (NC/4));
    int o  = r / (NC/4);
    int i4 = r % (NC/4);
    int p = 0;
    #pragma unroll
    for (int j = 0; j < 4; j++) {
        int i = i4*4 + j;
        float ws = W[(o*NC + i)*NK + k] * inv_beta;
        ws = fminf(fmaxf(ws, -1.f), 1.f);
        int q = (int)rintf(ws);
        p |= (q & 0xFF) << (8*j);
    }
    int ic = i4 >> 3, j8 = i4 & 7;                     // ic in 0..31
    ((int*)g_wq)[((k*32 + ic)*NC + o)*8 + j8] = p;
}

// ---------------- layernorm stats per row (b,t) ----------------
__global__ void k_lnstats(const float* __restrict__ x) {
    int row = blockIdx.x;
    int tid = threadIdx.x;
    const float* xr = x + (size_t)row * NC;
    float s = 0.f, s2 = 0.f;
    #pragma unroll
    for (int j = 0; j < 4; j++) {
        float v = xr[tid + j*256];
        s += v; s2 += v*v;
    }
    #pragma unroll
    for (int off = 16; off; off >>= 1) {
        s  += __shfl_xor_sync(0xFFFFFFFFu, s,  off);
        s2 += __shfl_xor_sync(0xFFFFFFFFu, s2, off);
    }
    __shared__ float rs[8], rq[8];
    if ((tid & 31) == 0) { rs[tid >> 5] = s; rq[tid >> 5] = s2; }
    __syncthreads();
    if (tid == 0) {
        float ts = 0.f, tq = 0.f;
        #pragma unroll
        for (int w = 0; w < 8; w++) { ts += rs[w]; tq += rq[w]; }
        float mu  = ts * (1.f/NC);
        float var = fmaxf(tq * (1.f/NC) - mu*mu, 0.f);
        g_mu[row]   = mu;
        g_rstd[row] = rsqrtf(var + 1e-5f);
    }
}

// ---------------- abs-max over T per (b,c) of normalized x ----------------
__global__ void k_absmax(const float* __restrict__ x,
                         const float* __restrict__ gamma,
                         const float* __restrict__ betaln) {
    int c  = blockIdx.x * blockDim.x + threadIdx.x;
    int b  = blockIdx.z;
    int t0 = blockIdx.y * 256;
    float gm = gamma[c], bb = betaln[c];
    const float* xp = x + ((size_t)(b*NT + t0)) * NC + c;
    const float* mup = g_mu   + b*NT + t0;
    const float* rsp = g_rstd + b*NT + t0;
    float m = 0.f;
    #pragma unroll 8
    for (int tt = 0; tt < 256; tt++) {
        float v = xp[(size_t)tt * NC];
        v = (v - mup[tt]) * rsp[tt] * gm + bb;
        m = fmaxf(m, fabsf(v));
    }
    atomicMax(&g_absmax[b*NC + c], __float_as_uint(m));
}

// ---------------- quantize + transpose x -> g_xq packed [b][ig][8+t] ----------------
__global__ void k_quantx(const float* __restrict__ x,
                         const float* __restrict__ gamma,
                         const float* __restrict__ betaln) {
    __shared__ signed char sq[32*36];
    int tid = threadIdx.x;
    int t0 = blockIdx.x * 32, c0 = blockIdx.y * 32, b = blockIdx.z;
    #pragma unroll
    for (int it = 0; it < 4; it++) {
        int l  = it*256 + tid;
        int tt = l >> 5, cc = l & 31;
        int t = t0 + tt, c = c0 + cc;
        int row = b*NT + t;
        float v = x[(size_t)row * NC + c];
        v = (v - g_mu[row]) * g_rstd[row] * gamma[c] + betaln[c];
        float am = fmaxf(__uint_as_float(g_absmax[b*NC + c]), 1e-5f);
        float q = rintf(v * (127.f / am));
        q = fminf(fmaxf(q, -127.f), 127.f);
        sq[cc*36 + tt] = (signed char)(int)q;
    }
    __syncthreads();
    int igl = tid >> 5, tt = tid & 31;
    int b0 = (int)sq[(igl*4+0)*36 + tt] & 0xFF;
    int b1 = (int)sq[(igl*4+1)*36 + tt] & 0xFF;
    int b2 = (int)sq[(igl*4+2)*36 + tt] & 0xFF;
    int b3 = (int)sq[(igl*4+3)*36 + tt] & 0xFF;
    int p = b0 | (b1 << 8) | (b2 << 16) | (b3 << 24);
    g_xq[((b*256) + (c0 >> 2) + igl) * XSTRIDE + 8 + t0 + tt] = p;
}

// ---------------- warp-specialized conv: IMMA warps + dp4a warps in one CTA ----------------

__device__ __forceinline__ void mma_s8(int& c0, int& c1, int& c2, int& c3,
                                       int a0, int a1, int a2, int a3,
                                       int b0, int b1) {
    asm volatile("mma.sync.aligned.m16n8k32.row.col.s32.s8.s8.s32 "
                 "{%0,%1,%2,%3}, {%4,%5,%6,%7}, {%8,%9}, {%0,%1,%2,%3};"
                 : "+r"(c0), "+r"(c1), "+r"(c2), "+r"(c3)
                 : "r"(a0), "r"(a1), "r"(a2), "r"(a3), "r"(b0), "r"(b1));
}
__device__ __forceinline__ void bulk_g2s(uint32_t dst, const void* src, uint32_t bytes, uint32_t mbar) {
    asm volatile("cp.async.bulk.shared::cta.global.mbarrier::complete_tx::bytes "
                 "[%0], [%1], %2, [%3];"
                 :: "r"(dst), "l"(src), "r"(bytes), "r"(mbar) : "memory");
}
__device__ __forceinline__ void mbar_init(uint32_t mbar, uint32_t count) {
    asm volatile("mbarrier.init.shared.b64 [%0], %1;" :: "r"(mbar), "r"(count) : "memory");
}
__device__ __forceinline__ void mbar_expect_tx(uint32_t mbar, uint32_t bytes) {
    asm volatile("mbarrier.arrive.expect_tx.shared.b64 _, [%0], %1;" :: "r"(mbar), "r"(bytes) : "memory");
}
__device__ __forceinline__ void mbar_wait(uint32_t mbar, uint32_t parity) {
    asm volatile("{\n\t"
                 ".reg .pred P;\n\t"
                 "WL_%=:\n\t"
                 "mbarrier.try_wait.parity.acquire.cta.shared::cta.b64 P, [%0], %1, 0x989680;\n\t"
                 "@P bra WD_%=;\n\t"
                 "bra WL_%=;\n\t"
                 "WD_%=:\n\t"
                 "}" :: "r"(mbar), "r"(parity) : "memory");
}

#define BSTRIDE 280                   // ints per B smem row (280 % 32 == 24, conflict-free)
#define BROWB   1088                  // bytes copied per B row (272 ints: t0-8 .. t0+263)
#define CHUNK_TX (3*4096 + 8*BROWB)   // 20992

__global__ void __launch_bounds__(512)
k_conv_ws(float* __restrict__ out) {
    __shared__ __align__(16) int sA[2][3072];      // [buf][(k*128+row)*8 + j]  12KB each
    __shared__ __align__(16) int sB[2][8*BSTRIDE]; // [buf][ig*280 + col], col 0 == t0-8
    __shared__ __align__(8)  unsigned long long s_mbar[2];

    int tid  = threadIdx.x;
    int lane = tid & 31, warp = tid >> 5;
    int t0 = blockIdx.x * 256;
    int o0 = blockIdx.y * 128;
    int b  = blockIdx.z;

    const char* wqb = (const char*)g_wq;
    const int*  xq  = g_xq;

    uint32_t sA0 = (uint32_t)__cvta_generic_to_shared(&sA[0][0]);
    uint32_t sB0 = (uint32_t)__cvta_generic_to_shared(&sB[0][0]);
    uint32_t mb0 = (uint32_t)__cvta_generic_to_shared(&s_mbar[0]);
    uint32_t mb1 = (uint32_t)__cvta_generic_to_shared(&s_mbar[1]);

    if (tid == 0) { mbar_init(mb0, 1); mbar_init(mb1, 1); }
    __syncthreads();

    auto issue = [&](int ic, int buf) {
        uint32_t mb = buf ? mb1 : mb0;
        uint32_t dA = sA0 + buf*12288;
        uint32_t dB = sB0 + buf*(8*BSTRIDE*4);
        mbar_expect_tx(mb, CHUNK_TX);
        #pragma unroll
        for (int k = 0; k < 3; k++) {
            const void* src = wqb + ((size_t)((k*32 + ic)*NC + o0) << 5);
            bulk_g2s(dA + k*4096, src, 4096, mb);
        }
        #pragma unroll
        for (int ig = 0; ig < 8; ig++) {
            const void* src = xq + (size_t)(b*256 + ic*8 + ig) * XSTRIDE + t0;
            bulk_g2s(dB + ig*(BSTRIDE*4), src, BROWB, mb);
        }
    };

    // shared accumulator storage: imma warps view as [mt][nt][4], dp4a as [s][16]
    int acc[64];
    #pragma unroll
    for (int i = 0; i < 64; i++) acc[i] = 0;

    int q = lane & 3, r = lane >> 2;
    int wm = warp & 3, wn = warp >> 2;          // imma warps (0..7)
    int w2m = (warp - 8) & 3, w2n = (warp >= 12) ? 1 : 0;  // dp4a warps (8..15)
    int ubase = w2n*64 + q*16;

    if (tid == 0) issue(0, 0);

    for (int ic = 0; ic < 32; ic++) {
        int buf = ic & 1;
        if (ic < 31 && tid == 0) issue(ic + 1, buf ^ 1);
        mbar_wait(buf ? mb1 : mb0, (ic >> 1) & 1);

        const int* A = sA[buf];
        const int* B = sB[buf];

        if (warp < 8) {
            // ---- IMMA half: cols t0 .. t0+127 ----
            #pragma unroll
            for (int k = 0; k < 3; k++) {
                int a[2][4];
                #pragma unroll
                for (int mt = 0; mt < 2; mt++) {
                    int rb = wm*32 + mt*16;
                    const int* Ak = A + (k << 10);
                    a[mt][0] = Ak[((rb + r)     << 3) + q];
                    a[mt][1] = Ak[((rb + 8 + r) << 3) + q];
                    a[mt][2] = Ak[((rb + r)     << 3) + 4 + q];
                    a[mt][3] = Ak[((rb + 8 + r) << 3) + 4 + q];
                }
                #pragma unroll
                for (int nt = 0; nt < 8; nt++) {
                    int col = wn*64 + nt*8 + r + k + 7;   // sB col 0 == t0-8
                    int b0 = B[q*BSTRIDE + col];
                    int b1 = B[(4 + q)*BSTRIDE + col];
                    #pragma unroll
                    for (int mt = 0; mt < 2; mt++) {
                        int* ac = &acc[(mt*8 + nt)*4];
                        mma_s8(ac[0], ac[1], ac[2], ac[3],
                               a[mt][0], a[mt][1], a[mt][2], a[mt][3], b0, b1);
                    }
                }
            }
        } else {
            // ---- dp4a half: cols t0+128 .. t0+255 ----
            #pragma unroll 1
            for (int j = 0; j < 8; j++) {
                int bb[24];
                #pragma unroll
                for (int i = 0; i < 6; i++) {
                    int4 v = *(const int4*)&B[j*BSTRIDE + 132 + ubase + 4*i];
                    bb[4*i+0] = v.x; bb[4*i+1] = v.y; bb[4*i+2] = v.z; bb[4*i+3] = v.w;
                }
                int a[3][4];
                #pragma unroll
                for (int k = 0; k < 3; k++)
                    #pragma unroll
                    for (int s = 0; s < 4; s++)
                        a[k][s] = A[((k*128 + w2m*32 + s*8 + r) << 3) + j];
                #pragma unroll
                for (int k = 0; k < 3; k++)
                    #pragma unroll
                    for (int s = 0; s < 4; s++)
                        #pragma unroll
                        for (int uu = 0; uu < 16; uu++)
                            acc[s*16 + uu] = __dp4a(a[k][s], bb[3 + uu + k], acc[s*16 + uu]);
            }
        }
        __syncthreads();
    }

    // ---- epilogue ----
    float beta = fmaxf((float)(g_beta_acc * (1.0 / (double)NWELEM)), 1e-5f);
    if (warp < 8) {
        #pragma unroll
        for (int mt = 0; mt < 2; mt++) {
            int ro = o0 + wm*32 + mt*16 + r;
            float s0 = beta * fmaxf(__uint_as_float(g_absmax[b*NC + ro]),     1e-5f) * (1.f/127.f);
            float s1 = beta * fmaxf(__uint_as_float(g_absmax[b*NC + ro + 8]), 1e-5f) * (1.f/127.f);
            #pragma unroll
            for (int nt = 0; nt < 8; nt++) {
                int t = t0 + wn*64 + nt*8 + q*2;
                float* p0 = out + ((size_t)(b*NT + t)) * NC;
                float* p1 = p0 + NC;
                const int* ac = &acc[(mt*8 + nt)*4];
                p0[ro]     = (float)ac[0] * s0;
                p1[ro]     = (float)ac[1] * s0;
                p0[ro + 8] = (float)ac[2] * s1;
                p1[ro + 8] = (float)ac[3] * s1;
            }
        }
    } else {
        int tb = t0 + 128 + ubase;
        #pragma unroll
        for (int s = 0; s < 4; s++) {
            int ro = o0 + w2m*32 + s*8 + r;
            float osc = beta * fmaxf(__uint_as_float(g_absmax[b*NC + ro]), 1e-5f) * (1.f/127.f);
            #pragma unroll
            for (int uu = 0; uu < 16; uu++) {
                int t = tb + uu;
                out[((size_t)(b*NT + t))*NC + ro] = (float)acc[s*16 + uu] * osc;
            }
        }
    }
}

// ---------------- launch ----------------
extern "C" void kernel_launch(void* const* d_in, const int* in_sizes, int n_in,
                              void* d_out, int out_size) {
    const float* x      = (const float*)d_in[0];   // [8,4096,1024]
    const float* gamma  = (const float*)d_in[1];   // [1024]
    const float* betaln = (const float*)d_in[2];   // [1024]
    const float* W      = (const float*)d_in[3];   // [1024,1024,3]
    float* out = (float*)d_out;

    k_init<<<64, 256>>>();
    k_wsum<<<1536, 256>>>(W);
    k_quantw<<<(NK*NC*(NC/4) + 255)/256, 256>>>(W);
    k_lnstats<<<NB*NT, 256>>>(x);
    k_absmax<<<dim3(NC/256, 16, NB), 256>>>(x, gamma, betaln);
    k_quantx<<<dim3(NT/32, NC/32, NB), 256>>>(x, gamma, betaln);
    k_conv_ws<<<dim3(NT/256, NC/128, NB), 512>>>(out);
}